// round 17
// baseline (speedup 1.0000x reference)
#include <cuda_runtime.h>
#include <math.h>
#include <stdint.h>

#define NT     20000
#define K1DIM  20001
#define BB     64
#define FF     128
#define TT     16
#define H4     1024
#define HD     256
#define EPSF   1e-5f

// sparse-G1
#define NS   74
#define RPS  271
#define ECAP 2560
// dense split-K
#define S2 16
#define S3 32
#define S4 8

// ---------------- scratch layout (floats) ---------------------------------
#define OFF_STATS  0            // 128
#define OFF_HT     128
#define OFF_H2T    65664
#define OFF_ENCT   131200
#define OFF_D1T    147584
#define OFF_P1S    213120       // 74*64*1024
#define OFF_P1U    5062784      // 74*1024
#define OFF_P1V    5138560
#define OFF_UT     5214336
#define OFF_VT     5215360
#define OFF_P2     5216384      // 16*64*1024
#define OFF_P3     6264960      // 32*64*256
#define OFF_P4     6789248      // 8*64*1024
#define SCRATCH_N  7313536

__device__ __align__(16) float g_scratch[SCRATCH_N];
__device__ int g_cnt[BB * NT];                    // cnt[b][k]
__device__ unsigned long long g_mask[NT];

// ---------------- helpers ---------------------------------------------------
__device__ __forceinline__ void ffma2(unsigned long long& c,
                                      unsigned long long a,
                                      unsigned long long b) {
    asm("fma.rn.f32x2 %0, %1, %2, %0;" : "+l"(c) : "l"(a), "l"(b));
}
__device__ __forceinline__ unsigned long long dup2(float v) {
    float2 t; t.x = v; t.y = v;
    return *reinterpret_cast<unsigned long long*>(&t);
}
__device__ __forceinline__ float gelu_exact(float x) {
    return 0.5f * x * (1.0f + erff(x * 0.70710678118654752f));
}

// ---------------- zero kernels ----------------------------------------------
__global__ void k_zero_cnt() {
    int i = blockIdx.x * blockDim.x + threadIdx.x;
    int stride = gridDim.x * blockDim.x;
    for (int t = i; t < BB * NT; t += stride) g_cnt[t] = 0;
}
__global__ void k_zero_mask() {
    int i = blockIdx.x * blockDim.x + threadIdx.x;
    if (i < NT) g_mask[i] = 0ull;
}

// ---------------- count (layout [b][k]) -------------------------------------
__global__ void k_count(const int* __restrict__ tags) {
    int r = blockIdx.x * blockDim.x + threadIdx.x;
    if (r >= BB * FF) return;
    int b = r / FF;
    const int* t = tags + r * TT;
    int v[TT];
#pragma unroll
    for (int i = 0; i < TT; i++) v[i] = t[i];
#pragma unroll
    for (int i = 0; i < TT; i++) {
        bool dup = false;
#pragma unroll
        for (int j = 0; j < TT; j++)
            if (j < i && v[j] == v[i]) dup = true;
        if (!dup) {
            atomicAdd(&g_cnt[b * NT + v[i]], 1);
            atomicOr(&g_mask[v[i]], 1ull << b);
        }
    }
}

// ---------------- stats: block per batch (coalesced, deterministic) ----------
__global__ void k_stats(const float* __restrict__ fc, float* __restrict__ yout) {
    int b = blockIdx.x;
    const int* row = &g_cnt[b * NT];
    int s = 0, s2 = 0;
    for (int k = threadIdx.x; k < NT; k += 256) {
        int c = row[k];
        s += c; s2 += c * c;
    }
    __shared__ int sh[256], sh2[256];
    sh[threadIdx.x] = s; sh2[threadIdx.x] = s2;
    __syncthreads();
    for (int o = 128; o > 0; o >>= 1) {
        if (threadIdx.x < o) { sh[threadIdx.x] += sh[threadIdx.x + o]; sh2[threadIdx.x] += sh2[threadIdx.x + o]; }
        __syncthreads();
    }
    if (threadIdx.x == 0) {
        float mu = (float)sh[0] / (float)NT;
        float var = (float)sh2[0] / (float)NT - mu * mu;
        g_scratch[OFF_STATS + 2 * b] = mu;
        g_scratch[OFF_STATS + 2 * b + 1] = rsqrtf(var + EPSF);
        yout[(long long)b * K1DIM] = fc[b] * 0.01f;
    }
}

// ---------------- k_y: elementwise coalesced ---------------------------------
__global__ void k_y(const float* __restrict__ lg, const float* __restrict__ lb,
                    float* __restrict__ yout) {
    int b = blockIdx.y;
    int k = blockIdx.x * 256 + threadIdx.x;
    if (k >= NT) return;
    float mu = g_scratch[OFF_STATS + 2 * b];
    float r  = g_scratch[OFF_STATS + 2 * b + 1];
    float c  = (float)g_cnt[b * NT + k];
    yout[(long long)b * K1DIM + 1 + k] = (c - mu) * r * lg[k] + lb[k];
}

// ---------------- g_sparse1: stream w1, scatter into smem S[64][256] --------
#define SPB_S    0          // 64*256*4 = 65536
#define SPB_ENT  65536      // ECAP int2 = 20480
#define SPB_OFF  86016      // 272 int
#define SPB_PC   87104      // 272 int
#define SPB_LG   88192      // 272 f
#define SPB_LB   89280      // 272 f
#define SPB_CTR  90368
#define SPB_TOT  90384

__global__ __launch_bounds__(256, 2) void g_sparse1(
    const float* __restrict__ w1, const float* __restrict__ lg,
    const float* __restrict__ lb) {
    extern __shared__ char sp[];
    float* S    = (float*)(sp + SPB_S);
    int2*  ent  = (int2*)(sp + SPB_ENT);
    int*   roff = (int*)(sp + SPB_OFF);
    int*   rpc  = (int*)(sp + SPB_PC);
    float* lgv  = (float*)(sp + SPB_LG);
    float* lbv  = (float*)(sp + SPB_LB);
    int*   ctr  = (int*)(sp + SPB_CTR);

    int tid = threadIdx.x;
    int jb = blockIdx.x * 256;
    int sl = blockIdx.y;
    int k0 = sl * RPS;
    int nR = min(RPS, NT - k0);

    if (tid == 0) *ctr = 0;
    for (int i = tid; i < 64 * 256; i += 256) S[i] = 0.f;
    __syncthreads();

    // prep: per-row entry lists (b, cnt*lg)
    for (int kl = tid; kl < nR; kl += 256) {
        int k = k0 + kl;
        float g = lg[k], bv = lb[k];
        lgv[kl] = g; lbv[kl] = bv;
        unsigned long long m = g_mask[k];
        int pc = __popcll(m);
        int off = 0;
        if (pc) off = atomicAdd(ctr, pc);
        if (off + pc > ECAP) pc = 0;          // safety (never expected)
        roff[kl] = off; rpc[kl] = pc;
        int i = 0;
        while (i < pc) {
            int b = __ffsll((long long)m) - 1; m &= m - 1;
            float c = (float)g_cnt[b * NT + k];
            ent[off + i] = make_int2(b, __float_as_int(c * g));
            i++;
        }
    }
    __syncthreads();

    float uacc = 0.f, vacc = 0.f;
    const float* wbase = w1 + (size_t)(k0 + 1) * H4 + jb + tid;

    int kl = 0;
    for (; kl + 8 <= nR; kl += 8) {
        float wv[8];
#pragma unroll
        for (int u = 0; u < 8; u++) wv[u] = wbase[(size_t)(kl + u) * H4];
#pragma unroll
        for (int u = 0; u < 8; u++) {
            int r = kl + u;
            uacc += lgv[r] * wv[u];
            vacc += lbv[r] * wv[u];
            int off = roff[r], pc = rpc[r];
            for (int e = 0; e < pc; e++) {
                int2 E = ent[off + e];
                S[E.x * 256 + tid] += __int_as_float(E.y) * wv[u];
            }
        }
    }
    for (; kl < nR; kl++) {
        float w = wbase[(size_t)kl * H4];
        uacc += lgv[kl] * w;
        vacc += lbv[kl] * w;
        int off = roff[kl], pc = rpc[kl];
        for (int e = 0; e < pc; e++) {
            int2 E = ent[off + e];
            S[E.x * 256 + tid] += __int_as_float(E.y) * w;
        }
    }
    __syncthreads();

    g_scratch[OFF_P1U + sl * H4 + jb + tid] = uacc;
    g_scratch[OFF_P1V + sl * H4 + jb + tid] = vacc;
    for (int b = 0; b < 64; b++)
        g_scratch[OFF_P1S + (size_t)(sl * 64 + b) * H4 + jb + tid] = S[b * 256 + tid];
}

// ---------------- k_uv: reduce u,v over slices ------------------------------
__global__ void k_uv() {
    int j = blockIdx.x * 256 + threadIdx.x;
    float su = 0.f, sv = 0.f;
    for (int s = 0; s < NS; s++) {
        su += g_scratch[OFF_P1U + s * H4 + j];
        sv += g_scratch[OFF_P1V + s * H4 + j];
    }
    g_scratch[OFF_UT + j] = su;
    g_scratch[OFF_VT + j] = sv;
}

// ---------------- k_eln: assemble enc1 + GELU + LayerNorm -> hT --------------
__global__ void k_eln(const float* __restrict__ b1, const float* __restrict__ lg2,
                      const float* __restrict__ lb2, const float* __restrict__ w1,
                      const float* __restrict__ fc) {
    int b = blockIdx.x;
    __shared__ float vals[H4];
    __shared__ float red[256];
    float mu_b = g_scratch[OFF_STATS + 2 * b];
    float r_b  = g_scratch[OFF_STATS + 2 * b + 1];
    float y0 = fc[b] * 0.01f;
    float ssum = 0.0f;
    for (int j = threadIdx.x; j < H4; j += 256) {
        float Sv = 0.f;
        for (int sl = 0; sl < NS; sl++)
            Sv += g_scratch[OFF_P1S + (size_t)(sl * 64 + b) * H4 + j];
        float x = b1[j] + r_b * Sv + g_scratch[OFF_VT + j]
                - mu_b * r_b * g_scratch[OFF_UT + j] + y0 * w1[j];
        float g = gelu_exact(x);
        vals[j] = g; ssum += g;
    }
    red[threadIdx.x] = ssum; __syncthreads();
    for (int o = 128; o > 0; o >>= 1) {
        if (threadIdx.x < o) red[threadIdx.x] += red[threadIdx.x + o];
        __syncthreads();
    }
    float mu = red[0] / (float)H4;
    __syncthreads();
    float s2 = 0.0f;
    for (int j = threadIdx.x; j < H4; j += 256) { float d = vals[j] - mu; s2 += d * d; }
    red[threadIdx.x] = s2; __syncthreads();
    for (int o = 128; o > 0; o >>= 1) {
        if (threadIdx.x < o) red[threadIdx.x] += red[threadIdx.x + o];
        __syncthreads();
    }
    float r = rsqrtf(red[0] / (float)H4 + EPSF);
    for (int j = threadIdx.x; j < H4; j += 256)
        g_scratch[OFF_HT + (long long)j * BB + b] = (vals[j] - mu) * r * lg2[j] + lb2[j];
}

// ---------------- dense tiled GEMM (measured baseline, + direct mode) --------
// mode 0: store partial[s][b][j] into g_scratch[p_off]
// mode 1: store final out_ext[b][j] = acc + bias[j]
__global__ __launch_bounds__(128, 3)
void k_gemm(int at_off, const float* __restrict__ W, int p_off,
            float* __restrict__ out_ext, const float* __restrict__ bias,
            int K, int N, int Ns, int kPerSlice, int mode) {
    __shared__ float ws[16][128];
    __shared__ float ys[16][64];
    const float* AT = &g_scratch[at_off];

    int jbase  = blockIdx.x * 128;
    int s      = blockIdx.y;
    int kstart = s * kPerSlice;
    int kend   = min(kstart + kPerSlice, K);
    int tid = threadIdx.x;
    int jg = tid & 15;
    int bg = tid >> 4;

    unsigned long long acc[4][8];
#pragma unroll
    for (int p = 0; p < 4; p++)
#pragma unroll
        for (int i = 0; i < 8; i++) acc[p][i] = 0ull;

    bool vecW = ((N & 3) == 0) && (jbase + 128 <= N);

    for (int kc = kstart; kc < kend; kc += 16) {
        if (vecW) {
#pragma unroll
            for (int i = 0; i < 4; i++) {
                int idx = tid + 128 * i;
                int row = idx >> 5, col = (idx & 31) * 4;
                int kg  = kc + row;
                float4 v = make_float4(0.f, 0.f, 0.f, 0.f);
                if (kg < kend)
                    v = *reinterpret_cast<const float4*>(&W[(long long)kg * N + jbase + col]);
                *reinterpret_cast<float4*>(&ws[row][col]) = v;
            }
        } else {
#pragma unroll
            for (int i = 0; i < 16; i++) {
                int idx = tid + 128 * i;
                int row = idx >> 7, col = idx & 127;
                int kg  = kc + row;
                int j   = jbase + col;
                ws[row][col] = (kg < kend && j < N) ? W[(long long)kg * N + j] : 0.0f;
            }
        }
#pragma unroll
        for (int i = 0; i < 2; i++) {
            int idx = tid + 128 * i;
            int row = idx >> 4, col = (idx & 15) * 4;
            int kg  = kc + row;
            float4 v = make_float4(0.f, 0.f, 0.f, 0.f);
            if (kg < kend)
                v = *reinterpret_cast<const float4*>(&AT[(long long)kg * BB + col]);
            *reinterpret_cast<float4*>(&ys[row][col]) = v;
        }
        __syncthreads();

#pragma unroll
        for (int kk = 0; kk < 16; kk++) {
            unsigned long long wv[4];
#pragma unroll
            for (int p = 0; p < 4; p++)
                wv[p] = *reinterpret_cast<const unsigned long long*>(&ws[kk][2 * (jg + 16 * p)]);
            float4 ya = *reinterpret_cast<const float4*>(&ys[kk][bg * 8]);
            float4 yb = *reinterpret_cast<const float4*>(&ys[kk][bg * 8 + 4]);
            unsigned long long yd[8];
            yd[0] = dup2(ya.x); yd[1] = dup2(ya.y); yd[2] = dup2(ya.z); yd[3] = dup2(ya.w);
            yd[4] = dup2(yb.x); yd[5] = dup2(yb.y); yd[6] = dup2(yb.z); yd[7] = dup2(yb.w);
#pragma unroll
            for (int p = 0; p < 4; p++)
#pragma unroll
                for (int i = 0; i < 8; i++)
                    ffma2(acc[p][i], wv[p], yd[i]);
        }
        __syncthreads();
    }

    if (mode == 0) {
        float* P = &g_scratch[p_off];
#pragma unroll
        for (int p = 0; p < 4; p++) {
            int j0 = jbase + 2 * (jg + 16 * p);
            if (j0 >= N) continue;
#pragma unroll
            for (int i = 0; i < 8; i++) {
                int b = bg * 8 + i;
                *reinterpret_cast<float2*>(&P[(long long)(s * BB + b) * Ns + j0]) =
                    *reinterpret_cast<float2*>(&acc[p][i]);
            }
        }
    } else {
#pragma unroll
        for (int p = 0; p < 4; p++) {
            int j0 = jbase + 2 * (jg + 16 * p);
            if (j0 >= N) continue;
            float bv0 = bias[j0];
            float bv1 = (j0 + 1 < N) ? bias[j0 + 1] : 0.f;
#pragma unroll
            for (int i = 0; i < 8; i++) {
                int b = bg * 8 + i;
                float2 f = *reinterpret_cast<float2*>(&acc[p][i]);
                out_ext[(long long)b * N + j0] = f.x + bv0;
                if (j0 + 1 < N) out_ext[(long long)b * N + j0 + 1] = f.y + bv1;
            }
        }
    }
}

// ---------------- epilogues --------------------------------------------------
__global__ void k_gelu_t(int p_off, int S, const float* __restrict__ bias,
                         int out_off, int N) {
    int idx = blockIdx.x * blockDim.x + threadIdx.x;
    if (idx >= BB * N) return;
    int b = idx / N, j = idx - b * N;
    float x = bias[j];
    for (int sl = 0; sl < S; sl++)
        x += g_scratch[p_off + (long long)(sl * BB + b) * N + j];
    g_scratch[out_off + (long long)j * BB + b] = gelu_exact(x);
}

__global__ void k_enc(const float* __restrict__ be2, float* __restrict__ enc_out) {
    int idx = blockIdx.x * blockDim.x + threadIdx.x;
    if (idx >= BB * HD) return;
    int b = idx / HD, j = idx - b * HD;
    float v = be2[j];
    for (int sl = 0; sl < S3; sl++)
        v += g_scratch[OFF_P3 + (long long)(sl * BB + b) * HD + j];
    enc_out[idx] = v;
    g_scratch[OFF_ENCT + (long long)j * BB + b] = v;
}

// ---------------------------------------------------------------------------
extern "C" void kernel_launch(void* const* d_in, const int* in_sizes, int n_in,
                              void* d_out, int out_size) {
    const int*   tags  = (const int*)d_in[0];
    const float* fc    = (const float*)d_in[1];
    const float* ln_g  = (const float*)d_in[2];
    const float* ln_b  = (const float*)d_in[3];
    const float* w1    = (const float*)d_in[4];
    const float* b1    = (const float*)d_in[5];
    const float* ln2_g = (const float*)d_in[6];
    const float* ln2_b = (const float*)d_in[7];
    const float* we1   = (const float*)d_in[8];
    const float* be1   = (const float*)d_in[9];
    const float* we2   = (const float*)d_in[10];
    const float* be2   = (const float*)d_in[11];
    const float* wd1   = (const float*)d_in[12];
    const float* bd1   = (const float*)d_in[13];
    const float* wd2   = (const float*)d_in[14];
    const float* bd2   = (const float*)d_in[15];

    float* out     = (float*)d_out;
    float* y_out   = out;                          // [64][20001]
    float* enc_out = out + (long long)BB * K1DIM;  // [64][256]
    float* dec_out = enc_out + (long long)BB * HD; // [64][20001]

    cudaFuncSetAttribute(g_sparse1, cudaFuncAttributeMaxDynamicSharedMemorySize, SPB_TOT);

    k_zero_cnt<<<512, 256>>>();                               // 1
    k_zero_mask<<<(NT + 255) / 256, 256>>>();                 // 2
    k_count<<<64, 128>>>(tags);                               // 3
    k_stats<<<BB, 256>>>(fc, y_out);                          // 4
    k_y<<<dim3((NT + 255) / 256, BB), 256>>>(ln_g, ln_b, y_out); // 5
    g_sparse1<<<dim3(4, NS), 256, SPB_TOT>>>(w1, ln_g, ln_b); // 6 (ncu target)
    k_uv<<<4, 256>>>();
    k_eln<<<BB, 256>>>(b1, ln2_g, ln2_b, w1, fc);

    // G2: h @ we1 -> P2
    k_gemm<<<dim3(8, S2), 128>>>(OFF_HT, we1, OFF_P2, nullptr, nullptr,
                                 H4, H4, H4, 64, 0);
    k_gelu_t<<<(BB * H4 + 255) / 256, 256>>>(OFF_P2, S2, be1, OFF_H2T, H4);

    // G3: h2 @ we2 -> P3
    k_gemm<<<dim3(2, S3), 128>>>(OFF_H2T, we2, OFF_P3, nullptr, nullptr,
                                 H4, HD, HD, 32, 0);
    k_enc<<<(BB * HD + 255) / 256, 256>>>(be2, enc_out);

    // G4: enc @ wd1 -> P4
    k_gemm<<<dim3(8, S4), 128>>>(OFF_ENCT, wd1, OFF_P4, nullptr, nullptr,
                                 HD, H4, H4, 32, 0);
    k_gelu_t<<<(BB * H4 + 255) / 256, 256>>>(OFF_P4, S4, bd1, OFF_D1T, H4);

    // G5: d1 @ wd2 -> dec_out directly + bias (157 blocks, full K; measured form)
    k_gemm<<<dim3(157, 1), 128>>>(OFF_D1T, wd2, 0, dec_out, bd2,
                                  H4, K1DIM, K1DIM, H4, 1);
}